// round 1
// baseline (speedup 1.0000x reference)
#include <cuda_runtime.h>
#include <math.h>

#define N_NODES 8192
#define N_EDGES 262144
#define N_TOT   (N_EDGES + N_NODES)

// ---------------- scratch (device globals; no cudaMalloc allowed) ----------
__device__ float g_xl[N_NODES * 256];
__device__ float g_xr[N_NODES * 256];
__device__ float g_h [N_NODES * 128];
__device__ float g_re[N_NODES * 128];
__device__ float g_xd[N_NODES * 128];
__device__ int   g_deg[N_NODES];
__device__ int   g_rowptr[N_NODES + 1];
__device__ int   g_cursor[N_NODES];
__device__ int   g_csrc[N_TOT];
__device__ int   g_w64;   // 1 if edge_index is int64, 0 if int32

// ---------------- CSR construction -----------------------------------------
__global__ void k_init_deg() {
    int i = blockIdx.x * blockDim.x + threadIdx.x;
    if (i == 0) g_w64 = 1;
    if (i < N_NODES) g_deg[i] = 1;   // self loop
}

// If the buffer is actually int32, the odd 32-bit words are independent random
// values in [0,8192) and are almost surely not all zero. If int64, every odd
// word is a zero high-half.
__global__ void k_detect(const unsigned int* __restrict__ w) {
    int i = blockIdx.x * blockDim.x + threadIdx.x;
    if (i < N_EDGES) {
        if (w[2 * i + 1] != 0u) g_w64 = 0;
    }
}

__device__ __forceinline__ int load_idx(const void* ei, int pos) {
    if (g_w64) return (int)((const long long*)ei)[pos];
    return ((const int*)ei)[pos];
}

__global__ void k_hist(const void* __restrict__ ei) {
    int e = blockIdx.x * blockDim.x + threadIdx.x;
    if (e < N_EDGES) {
        int d = load_idx(ei, N_EDGES + e);
        atomicAdd(&g_deg[d], 1);
    }
}

__global__ void k_scan() {
    __shared__ int sums[1024];
    int tid = threadIdx.x;
    int base = tid * 8;
    int local[8];
    int run = 0;
#pragma unroll
    for (int j = 0; j < 8; j++) { local[j] = run; run += g_deg[base + j]; }
    sums[tid] = run;
    __syncthreads();
    for (int off = 1; off < 1024; off <<= 1) {
        int v = (tid >= off) ? sums[tid - off] : 0;
        __syncthreads();
        sums[tid] += v;
        __syncthreads();
    }
    int prefix = (tid == 0) ? 0 : sums[tid - 1];
#pragma unroll
    for (int j = 0; j < 8; j++) {
        int v = prefix + local[j];
        g_rowptr[base + j] = v;
        g_cursor[base + j] = v;
    }
    if (tid == 1023) g_rowptr[N_NODES] = prefix + run;
}

__global__ void k_fill_edges(const void* __restrict__ ei) {
    int e = blockIdx.x * blockDim.x + threadIdx.x;
    if (e < N_EDGES) {
        int s = load_idx(ei, e);
        int d = load_idx(ei, N_EDGES + e);
        int pos = atomicAdd(&g_cursor[d], 1);
        g_csrc[pos] = s;
    }
}

__global__ void k_fill_loops() {
    int i = blockIdx.x * blockDim.x + threadIdx.x;
    if (i < N_NODES) {
        int pos = atomicAdd(&g_cursor[i], 1);
        g_csrc[pos] = i;
    }
}

// ---------------- small GEMM: C[M,Nc] = A[M,K] * W[Nc,K]^T ------------------
__global__ __launch_bounds__(256) void k_gemm64(
    const float* __restrict__ A, const float* __restrict__ W,
    float* __restrict__ C, int M, int Nc, int K)
{
    __shared__ float As[16][64];
    __shared__ float Ws[16][64];
    int tid = threadIdx.x;
    int tx = tid & 15, ty = tid >> 4;
    int rowBase = blockIdx.y * 64, colBase = blockIdx.x * 64;
    int lr = tid >> 2;          // 0..63
    int lk = (tid & 3) * 4;     // 0,4,8,12
    float acc[4][4] = {};

    for (int kb = 0; kb < K; kb += 16) {
        float4 av = *(const float4*)&A[(size_t)(rowBase + lr) * K + kb + lk];
        float4 wv = *(const float4*)&W[(size_t)(colBase + lr) * K + kb + lk];
        As[lk + 0][lr] = av.x; As[lk + 1][lr] = av.y;
        As[lk + 2][lr] = av.z; As[lk + 3][lr] = av.w;
        Ws[lk + 0][lr] = wv.x; Ws[lk + 1][lr] = wv.y;
        Ws[lk + 2][lr] = wv.z; Ws[lk + 3][lr] = wv.w;
        __syncthreads();
#pragma unroll
        for (int k = 0; k < 16; k++) {
            float4 a = *(const float4*)&As[k][ty * 4];
            float4 b = *(const float4*)&Ws[k][tx * 4];
            float aa[4] = {a.x, a.y, a.z, a.w};
            float bb[4] = {b.x, b.y, b.z, b.w};
#pragma unroll
            for (int i = 0; i < 4; i++) {
#pragma unroll
                for (int j = 0; j < 4; j++) acc[i][j] += aa[i] * bb[j];
            }
        }
        __syncthreads();
    }
#pragma unroll
    for (int i = 0; i < 4; i++) {
#pragma unroll
        for (int j = 0; j < 4; j++) {
            C[(size_t)(rowBase + ty * 4 + i) * Nc + colBase + tx * 4 + j] = acc[i][j];
        }
    }
}

// ---------------- GATv2 edge softmax + aggregate (one warp per dst node) ----
template <int CPL>
__global__ __launch_bounds__(256) void k_agg(
    const float* __restrict__ xl, const float* __restrict__ xr,
    const float* __restrict__ att, const float* __restrict__ bias,
    float* __restrict__ out)
{
    const int CH = CPL * 32;
    int warp = blockIdx.x * (blockDim.x >> 5) + (threadIdx.x >> 5);
    int lane = threadIdx.x & 31;
    if (warp >= N_NODES) return;

    float xrv[CPL], av[CPL], acc[CPL];
#pragma unroll
    for (int c = 0; c < CPL; c++) {
        int ch = lane + c * 32;
        xrv[c] = xr[(size_t)warp * CH + ch];
        av[c]  = att[ch];
        acc[c] = 0.f;
    }
    float m = -3.0e38f, s = 0.f;
    int beg = g_rowptr[warp], end = g_rowptr[warp + 1];
    for (int e = beg; e < end; e++) {
        int src = g_csrc[e];
        float xs[CPL];
        float part = 0.f;
#pragma unroll
        for (int c = 0; c < CPL; c++) {
            xs[c] = xl[(size_t)src * CH + lane + c * 32];
            float t = xs[c] + xrv[c];
            float lr = t > 0.f ? t : 0.2f * t;
            part += av[c] * lr;
        }
#pragma unroll
        for (int o = 16; o > 0; o >>= 1)
            part += __shfl_xor_sync(0xffffffffu, part, o);
        float mn = fmaxf(m, part);
        float sc = __expf(m - mn);
        float p  = __expf(part - mn);
        s = s * sc + p;
#pragma unroll
        for (int c = 0; c < CPL; c++) acc[c] = acc[c] * sc + p * xs[c];
        m = mn;
    }
    float inv = 1.f / s;
#pragma unroll
    for (int c = 0; c < CPL; c++) {
        int ch = lane + c * 32;
        float v = acc[c] * inv + bias[ch];
        out[(size_t)warp * CH + ch] = fmaxf(v, 0.f);
    }
}

// ---------------- recon: out = sigmoid(R @ R^T), R = [8192,128] -------------
__global__ __launch_bounds__(256) void k_recon(
    const float* __restrict__ R, float* __restrict__ out)
{
    __shared__ float As[16][128];
    __shared__ float Bs[16][128];
    int tid = threadIdx.x;
    int tx = tid & 15, ty = tid >> 4;
    int rowBase = blockIdx.y * 128, colBase = blockIdx.x * 128;
    float acc[8][8] = {};

    for (int kb = 0; kb < 128; kb += 16) {
#pragma unroll
        for (int t = 0; t < 2; t++) {
            int id = tid + t * 256;      // 0..511
            int r  = id >> 2;            // 0..127
            int kq = (id & 3) * 4;       // 0,4,8,12
            float4 avv = *(const float4*)&R[(size_t)(rowBase + r) * 128 + kb + kq];
            float4 bvv = *(const float4*)&R[(size_t)(colBase + r) * 128 + kb + kq];
            As[kq + 0][r] = avv.x; As[kq + 1][r] = avv.y;
            As[kq + 2][r] = avv.z; As[kq + 3][r] = avv.w;
            Bs[kq + 0][r] = bvv.x; Bs[kq + 1][r] = bvv.y;
            Bs[kq + 2][r] = bvv.z; Bs[kq + 3][r] = bvv.w;
        }
        __syncthreads();
#pragma unroll
        for (int k = 0; k < 16; k++) {
            float4 a0 = *(const float4*)&As[k][ty * 8];
            float4 a1 = *(const float4*)&As[k][ty * 8 + 4];
            float4 b0 = *(const float4*)&Bs[k][tx * 8];
            float4 b1 = *(const float4*)&Bs[k][tx * 8 + 4];
            float a[8] = {a0.x, a0.y, a0.z, a0.w, a1.x, a1.y, a1.z, a1.w};
            float b[8] = {b0.x, b0.y, b0.z, b0.w, b1.x, b1.y, b1.z, b1.w};
#pragma unroll
            for (int i = 0; i < 8; i++) {
#pragma unroll
                for (int j = 0; j < 8; j++) acc[i][j] += a[i] * b[j];
            }
        }
        __syncthreads();
    }
#pragma unroll
    for (int i = 0; i < 8; i++) {
        size_t row = rowBase + ty * 8 + i;
        float4 v0, v1;
        v0.x = 1.f / (1.f + __expf(-acc[i][0]));
        v0.y = 1.f / (1.f + __expf(-acc[i][1]));
        v0.z = 1.f / (1.f + __expf(-acc[i][2]));
        v0.w = 1.f / (1.f + __expf(-acc[i][3]));
        v1.x = 1.f / (1.f + __expf(-acc[i][4]));
        v1.y = 1.f / (1.f + __expf(-acc[i][5]));
        v1.z = 1.f / (1.f + __expf(-acc[i][6]));
        v1.w = 1.f / (1.f + __expf(-acc[i][7]));
        *(float4*)&out[row * 8192 + colBase + tx * 8]     = v0;
        *(float4*)&out[row * 8192 + colBase + tx * 8 + 4] = v1;
    }
}

// ---------------- launcher ---------------------------------------------------
extern "C" void kernel_launch(void* const* d_in, const int* in_sizes, int n_in,
                              void* d_out, int out_size)
{
    const float* x  = (const float*)d_in[0];
    const void*  ei = d_in[1];
    const float* w1l = (const float*)d_in[2],  *w1r = (const float*)d_in[3];
    const float* a1  = (const float*)d_in[4],  *b1  = (const float*)d_in[5];
    const float* w2l = (const float*)d_in[6],  *w2r = (const float*)d_in[7];
    const float* a2  = (const float*)d_in[8],  *b2  = (const float*)d_in[9];
    const float* w3l = (const float*)d_in[10], *w3r = (const float*)d_in[11];
    const float* a3  = (const float*)d_in[12], *b3  = (const float*)d_in[13];
    const float* w4l = (const float*)d_in[14], *w4r = (const float*)d_in[15];
    const float* a4  = (const float*)d_in[16], *b4  = (const float*)d_in[17];
    const float* w5l = (const float*)d_in[18], *w5r = (const float*)d_in[19];
    const float* a5  = (const float*)d_in[20], *b5  = (const float*)d_in[21];

    float* out      = (float*)d_out;
    float* xrec_out = out + (size_t)8192 * 8192;                 // [8192,256]
    float* z_out    = out + (size_t)8192 * 8192 + 8192 * 256;    // [8192,256]

    float *xl, *xr, *h, *re, *xd;
    cudaGetSymbolAddress((void**)&xl, g_xl);
    cudaGetSymbolAddress((void**)&xr, g_xr);
    cudaGetSymbolAddress((void**)&h,  g_h);
    cudaGetSymbolAddress((void**)&re, g_re);
    cudaGetSymbolAddress((void**)&xd, g_xd);

    // CSR build
    k_init_deg<<<(N_NODES + 255) / 256, 256>>>();
    k_detect<<<(N_EDGES + 255) / 256, 256>>>((const unsigned int*)ei);
    k_hist<<<(N_EDGES + 255) / 256, 256>>>(ei);
    k_scan<<<1, 1024>>>();
    k_fill_edges<<<(N_EDGES + 255) / 256, 256>>>(ei);
    k_fill_loops<<<(N_NODES + 255) / 256, 256>>>();

    // Layer 1: in 256 -> out 128
    k_gemm64<<<dim3(2, 128), 256>>>(x, w1l, xl, 8192, 128, 256);
    k_gemm64<<<dim3(2, 128), 256>>>(x, w1r, xr, 8192, 128, 256);
    k_agg<4><<<1024, 256>>>(xl, xr, a1, b1, h);

    // Layer 2: in 128 -> out 256  (z, written straight into d_out)
    k_gemm64<<<dim3(4, 128), 256>>>(h, w2l, xl, 8192, 256, 128);
    k_gemm64<<<dim3(4, 128), 256>>>(h, w2r, xr, 8192, 256, 128);
    k_agg<8><<<1024, 256>>>(xl, xr, a2, b2, z_out);

    // Layer 3: in 256 -> out 128 (re)
    k_gemm64<<<dim3(2, 128), 256>>>(z_out, w3l, xl, 8192, 128, 256);
    k_gemm64<<<dim3(2, 128), 256>>>(z_out, w3r, xr, 8192, 128, 256);
    k_agg<4><<<1024, 256>>>(xl, xr, a3, b3, re);

    // recon_edge = sigmoid(re @ re.T)
    k_recon<<<dim3(64, 64), 256>>>(re, out);

    // Layer 4: in 256 -> out 128 (xd)
    k_gemm64<<<dim3(2, 128), 256>>>(z_out, w4l, xl, 8192, 128, 256);
    k_gemm64<<<dim3(2, 128), 256>>>(z_out, w4r, xr, 8192, 128, 256);
    k_agg<4><<<1024, 256>>>(xl, xr, a4, b4, xd);

    // Layer 5: in 128 -> out 256 (x_rec, straight into d_out)
    k_gemm64<<<dim3(4, 128), 256>>>(xd, w5l, xl, 8192, 256, 128);
    k_gemm64<<<dim3(4, 128), 256>>>(xd, w5r, xr, 8192, 256, 128);
    k_agg<8><<<1024, 256>>>(xl, xr, a5, b5, xrec_out);
}

// round 5
// speedup vs baseline: 1.9877x; 1.9877x over previous
#include <cuda_runtime.h>
#include <cuda_bf16.h>
#include <math.h>
#include <stdint.h>

#define N_NODES 8192
#define N_EDGES 262144
#define N_TOT   (N_EDGES + N_NODES)

// ---------------- scratch (device globals; no cudaMalloc allowed) ----------
__device__ __align__(128) __nv_bfloat16 g_actA[8192 * 768];   // A-layout splits
__device__ __align__(128) __nv_bfloat16 g_reB [8192 * 384];   // B-layout split of re
__device__ __align__(128) __nv_bfloat16 g_wB  [10 * 98304];   // B-layout weight splits
__device__ __align__(128) float g_xlr[8192 * 512];
__device__ __align__(128) float g_h  [8192 * 128];
__device__ __align__(128) float g_re [8192 * 128];
__device__ __align__(128) float g_xd [8192 * 128];
__device__ int g_deg[N_NODES];
__device__ int g_rowptr[N_NODES + 1];
__device__ int g_cursor[N_NODES];
__device__ int g_csrc[N_TOT];
__device__ int g_w64;

// ---------------- helpers ----------------------------------------------------
__device__ __forceinline__ uint32_t smem_u32(const void* p) {
    uint32_t a;
    asm("{ .reg .u64 t; cvta.to.shared.u64 t, %1; cvt.u32.u64 %0, t; }" : "=r"(a) : "l"(p));
    return a;
}
__device__ __forceinline__ void cp16(uint32_t dst, const void* src) {
    asm volatile("cp.async.cg.shared.global [%0], [%1], 16;" :: "r"(dst), "l"(src));
}
__device__ __forceinline__ void cp_commit() {
    asm volatile("cp.async.commit_group;" ::: "memory");
}
template <int N>
__device__ __forceinline__ void cp_wait() {
    asm volatile("cp.async.wait_group %0;" :: "n"(N) : "memory");
}
__device__ __forceinline__ void ldm4(uint32_t* r, uint32_t addr) {
    asm volatile("ldmatrix.sync.aligned.m8n8.x4.shared.b16 {%0,%1,%2,%3}, [%4];"
                 : "=r"(r[0]), "=r"(r[1]), "=r"(r[2]), "=r"(r[3]) : "r"(addr));
}
__device__ __forceinline__ void mma16816(float* c, const uint32_t* a, uint32_t b0, uint32_t b1) {
    asm volatile(
        "mma.sync.aligned.m16n8k16.row.col.f32.bf16.bf16.f32 "
        "{%0,%1,%2,%3}, {%4,%5,%6,%7}, {%8,%9}, {%0,%1,%2,%3};"
        : "+f"(c[0]), "+f"(c[1]), "+f"(c[2]), "+f"(c[3])
        : "r"(a[0]), "r"(a[1]), "r"(a[2]), "r"(a[3]), "r"(b0), "r"(b1));
}

// ---------------- CSR construction -----------------------------------------
__global__ void k_init_deg() {
    int i = blockIdx.x * blockDim.x + threadIdx.x;
    if (i == 0) g_w64 = 1;
    if (i < N_NODES) g_deg[i] = 1;
}
__global__ void k_detect(const unsigned int* __restrict__ w) {
    int i = blockIdx.x * blockDim.x + threadIdx.x;
    if (i < N_EDGES) {
        if (w[2 * i + 1] != 0u) g_w64 = 0;
    }
}
__device__ __forceinline__ int load_idx(const void* ei, int pos) {
    if (g_w64) return (int)((const long long*)ei)[pos];
    return ((const int*)ei)[pos];
}
__global__ void k_hist(const void* __restrict__ ei) {
    int e = blockIdx.x * blockDim.x + threadIdx.x;
    if (e < N_EDGES) atomicAdd(&g_deg[load_idx(ei, N_EDGES + e)], 1);
}
__global__ void k_scan() {
    __shared__ int wsum[32];
    int tid = threadIdx.x;
    int lane = tid & 31, w = tid >> 5;
    int base = tid * 8;
    int local[8];
    int run = 0;
#pragma unroll
    for (int j = 0; j < 8; j++) { local[j] = run; run += g_deg[base + j]; }
    int v = run;
#pragma unroll
    for (int o = 1; o < 32; o <<= 1) {
        int t = __shfl_up_sync(0xffffffffu, v, o);
        if (lane >= o) v += t;
    }
    if (lane == 31) wsum[w] = v;
    __syncthreads();
    if (w == 0) {
        int t = wsum[lane];
#pragma unroll
        for (int o = 1; o < 32; o <<= 1) {
            int u = __shfl_up_sync(0xffffffffu, t, o);
            if (lane >= o) t += u;
        }
        wsum[lane] = t;
    }
    __syncthreads();
    int exc = ((w == 0) ? 0 : wsum[w - 1]) + v - run;
#pragma unroll
    for (int j = 0; j < 8; j++) {
        g_rowptr[base + j] = exc + local[j];
        g_cursor[base + j] = exc + local[j];
    }
    if (tid == 1023) g_rowptr[N_NODES] = exc + run;
}
__global__ void k_fill_edges(const void* __restrict__ ei) {
    int e = blockIdx.x * blockDim.x + threadIdx.x;
    if (e < N_EDGES) {
        int s = load_idx(ei, e);
        int d = load_idx(ei, N_EDGES + e);
        g_csrc[atomicAdd(&g_cursor[d], 1)] = s;
    }
}
__global__ void k_fill_loops() {
    int i = blockIdx.x * blockDim.x + threadIdx.x;
    if (i < N_NODES) g_csrc[atomicAdd(&g_cursor[i], 1)] = i;
}

// ---------------- split-precision conversion --------------------------------
// A-layout: [hi | lo | hi], B-layout: [hi | hi | lo]  (3K columns each)
__global__ void k_split_act(const float* __restrict__ src,
                            __nv_bfloat16* __restrict__ dstA,
                            __nv_bfloat16* __restrict__ dstB, int K) {
    int idx = blockIdx.x * blockDim.x + threadIdx.x;
    int m = idx / K, k = idx - m * K;
    float v = src[idx];
    __nv_bfloat16 hi = __float2bfloat16(v);
    __nv_bfloat16 lo = __float2bfloat16(v - __bfloat162float(hi));
    size_t b = (size_t)m * 3 * K + k;
    dstA[b] = hi; dstA[b + K] = lo; dstA[b + 2 * K] = hi;
    if (dstB) { dstB[b] = hi; dstB[b + K] = hi; dstB[b + 2 * K] = lo; }
}
__constant__ int c_wK[10] = {256, 256, 128, 128, 256, 256, 256, 256, 128, 128};
__global__ void k_split_w(const float* w0, const float* w1, const float* w2,
                          const float* w3, const float* w4, const float* w5,
                          const float* w6, const float* w7, const float* w8,
                          const float* w9) {
    const float* ws[10] = {w0, w1, w2, w3, w4, w5, w6, w7, w8, w9};
    int mid = blockIdx.x >> 7;
    int idx = (blockIdx.x & 127) * 256 + threadIdx.x;
    int K = c_wK[mid];
    int n = idx / K, k = idx - n * K;
    float v = ws[mid][idx];
    __nv_bfloat16 hi = __float2bfloat16(v);
    __nv_bfloat16 lo = __float2bfloat16(v - __bfloat162float(hi));
    __nv_bfloat16* dst = g_wB + (size_t)mid * 98304;
    size_t b = (size_t)n * 3 * K + k;
    dst[b] = hi; dst[b + K] = hi; dst[b + 2 * K] = lo;
}

// ---------------- HMMA GEMM: C[M,Nc] = A[M,Kp] * B[Nc,Kp]^T -----------------
// block tile 128x128, 8 warps (32x64 each), K-chunk 64, SW128 smem, cp.async.
// SYM: only upper-triangle tiles computed; mirror written via smem transpose.
#define SMEM_GEMM 65536

template <bool SIG, bool SYM>
__global__ void __launch_bounds__(256) k_mma(
    const __nv_bfloat16* __restrict__ A, const __nv_bfloat16* __restrict__ B,
    float* __restrict__ C, int Kp, int ldc)
{
    if (SYM && blockIdx.y > blockIdx.x) return;
    extern __shared__ char smem[];
    uint32_t sb = smem_u32(smem);
    const int tid = threadIdx.x;
    const int wid = tid >> 5, lane = tid & 31;
    const int m_base = (wid >> 1) * 32;      // warp row within tile
    const int n_base = (wid & 1) * 64;       // warp col within tile
    const int rowBase = blockIdx.y * 128;
    const int colBase = blockIdx.x * 128;

    float acc[2][8][4];
#pragma unroll
    for (int mi = 0; mi < 2; mi++)
#pragma unroll
        for (int ni = 0; ni < 8; ni++)
#pragma unroll
            for (int j = 0; j < 4; j++) acc[mi][ni][j] = 0.f;

#define LOADC(buf, ck) do {                                                    \
    const __nv_bfloat16* Ag = A + (size_t)rowBase * Kp + (ck) * 64;            \
    _Pragma("unroll")                                                          \
    for (int i = 0; i < 4; i++) {                                              \
        int idx = tid + i * 256;                                               \
        int r = idx >> 3, q = idx & 7;                                         \
        uint32_t off = (uint32_t)(r * 128 + q * 16);                           \
        off ^= (off >> 3) & 0x70;                                              \
        cp16(sb + (buf) * 16384 + off,                                         \
             (const char*)Ag + (size_t)r * Kp * 2 + q * 16);                   \
    }                                                                          \
    const __nv_bfloat16* Bg = B + (size_t)colBase * Kp + (ck) * 64;            \
    _Pragma("unroll")                                                          \
    for (int i = 0; i < 4; i++) {                                              \
        int idx = tid + i * 256;                                               \
        int r = idx >> 3, q = idx & 7;                                         \
        uint32_t off = (uint32_t)(r * 128 + q * 16);                           \
        off ^= (off >> 3) & 0x70;                                              \
        cp16(sb + 32768 + (buf) * 16384 + off,                                 \
             (const char*)Bg + (size_t)r * Kp * 2 + q * 16);                   \
    }                                                                          \
    cp_commit();                                                               \
} while (0)

    const int nc = Kp >> 6;
    LOADC(0, 0);
    for (int c = 0; c < nc; c++) {
        int buf = c & 1;
        if (c + 1 < nc) { LOADC(buf ^ 1, c + 1); cp_wait<1>(); }
        else cp_wait<0>();
        __syncthreads();
        uint32_t sbA = sb + buf * 16384;
        uint32_t sbB = sb + 32768 + buf * 16384;
#pragma unroll
        for (int ks = 0; ks < 4; ks++) {
            uint32_t a[2][4];
#pragma unroll
            for (int mi = 0; mi < 2; mi++) {
                uint32_t off = (uint32_t)((m_base + mi * 16 + (lane & 15)) * 128
                                          + ks * 32 + ((lane >> 4) << 4));
                off ^= (off >> 3) & 0x70;
                ldm4(a[mi], sbA + off);
            }
            uint32_t b[4][4];
#pragma unroll
            for (int p = 0; p < 4; p++) {
                uint32_t off = (uint32_t)((n_base + p * 16 + (lane & 7) + ((lane >> 4) << 3)) * 128
                                          + ks * 32 + (((lane >> 3) & 1) << 4));
                off ^= (off >> 3) & 0x70;
                ldm4(b[p], sbB + off);
            }
#pragma unroll
            for (int mi = 0; mi < 2; mi++)
#pragma unroll
                for (int ni = 0; ni < 8; ni++)
                    mma16816(acc[mi][ni], a[mi], b[ni >> 1][(ni & 1) * 2],
                             b[ni >> 1][(ni & 1) * 2 + 1]);
        }
        __syncthreads();
    }

    if (SIG) {
#pragma unroll
        for (int mi = 0; mi < 2; mi++)
#pragma unroll
            for (int ni = 0; ni < 8; ni++)
#pragma unroll
                for (int j = 0; j < 4; j++)
                    acc[mi][ni][j] = 1.f / (1.f + __expf(-acc[mi][ni][j]));
    }

    // normal (row-major) write
#pragma unroll
    for (int mi = 0; mi < 2; mi++) {
        int gr = rowBase + m_base + mi * 16 + (lane >> 2);
#pragma unroll
        for (int ni = 0; ni < 8; ni++) {
            int gc = colBase + n_base + ni * 8 + (lane & 3) * 2;
            *(float2*)&C[(size_t)gr * ldc + gc] = make_float2(acc[mi][ni][0], acc[mi][ni][1]);
            *(float2*)&C[(size_t)(gr + 8) * ldc + gc] = make_float2(acc[mi][ni][2], acc[mi][ni][3]);
        }
    }

    if (SYM) {
        // mirrored write via smem transpose (64 n-rows per pass, stride 132)
        float* sT = (float*)smem;
#pragma unroll
        for (int nh = 0; nh < 2; nh++) {
            __syncthreads();
            if ((wid & 1) == nh) {
#pragma unroll
                for (int mi = 0; mi < 2; mi++) {
                    int ml = m_base + mi * 16 + (lane >> 2);
#pragma unroll
                    for (int ni = 0; ni < 8; ni++) {
                        int cl = ni * 8 + (lane & 3) * 2;
                        sT[cl * 132 + ml]           = acc[mi][ni][0];
                        sT[(cl + 1) * 132 + ml]     = acc[mi][ni][1];
                        sT[cl * 132 + ml + 8]       = acc[mi][ni][2];
                        sT[(cl + 1) * 132 + ml + 8] = acc[mi][ni][3];
                    }
                }
            }
            __syncthreads();
            int n_loc = tid >> 2;
#pragma unroll
            for (int it = 0; it < 8; it++) {
                int m4 = (tid & 3) * 32 + it * 4;
                float4 v = *(float4*)&sT[n_loc * 132 + m4];
                *(float4*)&C[(size_t)(colBase + nh * 64 + n_loc) * ldc + rowBase + m4] = v;
            }
        }
    }
#undef LOADC
}

// ---------------- GATv2 edge softmax + aggregate (one warp per dst node) ----
template <int CPL>
__global__ __launch_bounds__(256) void k_agg(
    const float* __restrict__ xlr, int S, int xrOff,
    const float* __restrict__ att, const float* __restrict__ bias,
    float* __restrict__ out)
{
    const int CH = CPL * 32;
    int warp = blockIdx.x * (blockDim.x >> 5) + (threadIdx.x >> 5);
    int lane = threadIdx.x & 31;
    if (warp >= N_NODES) return;

    float xrv[CPL], av[CPL], acc[CPL];
#pragma unroll
    for (int c = 0; c < CPL; c++) {
        int ch = lane + c * 32;
        xrv[c] = xlr[(size_t)warp * S + xrOff + ch];
        av[c]  = att[ch];
        acc[c] = 0.f;
    }
    float m = -3.0e38f, s = 0.f;
    int beg = g_rowptr[warp], end = g_rowptr[warp + 1];
    for (int e = beg; e < end; e++) {
        int src = g_csrc[e];
        float xs[CPL];
        float part = 0.f;
#pragma unroll
        for (int c = 0; c < CPL; c++) {
            xs[c] = xlr[(size_t)src * S + lane + c * 32];
            float t = xs[c] + xrv[c];
            float lr = t > 0.f ? t : 0.2f * t;
            part += av[c] * lr;
        }
#pragma unroll
        for (int o = 16; o > 0; o >>= 1)
            part += __shfl_xor_sync(0xffffffffu, part, o);
        float mn = fmaxf(m, part);
        float sc = __expf(m - mn);
        float p  = __expf(part - mn);
        s = s * sc + p;
#pragma unroll
        for (int c = 0; c < CPL; c++) acc[c] = acc[c] * sc + p * xs[c];
        m = mn;
    }
    float inv = 1.f / s;
#pragma unroll
    for (int c = 0; c < CPL; c++) {
        int ch = lane + c * 32;
        float v = acc[c] * inv + bias[ch];
        out[(size_t)warp * CH + ch] = fmaxf(v, 0.f);
    }
}

// ---------------- launcher ---------------------------------------------------
extern "C" void kernel_launch(void* const* d_in, const int* in_sizes, int n_in,
                              void* d_out, int out_size)
{
    const float* x  = (const float*)d_in[0];
    const void*  ei = d_in[1];
    const float* w1l = (const float*)d_in[2],  *w1r = (const float*)d_in[3];
    const float* a1  = (const float*)d_in[4],  *b1  = (const float*)d_in[5];
    const float* w2l = (const float*)d_in[6],  *w2r = (const float*)d_in[7];
    const float* a2  = (const float*)d_in[8],  *b2  = (const float*)d_in[9];
    const float* w3l = (const float*)d_in[10], *w3r = (const float*)d_in[11];
    const float* a3  = (const float*)d_in[12], *b3  = (const float*)d_in[13];
    const float* w4l = (const float*)d_in[14], *w4r = (const float*)d_in[15];
    const float* a4  = (const float*)d_in[16], *b4  = (const float*)d_in[17];
    const float* w5l = (const float*)d_in[18], *w5r = (const float*)d_in[19];
    const float* a5  = (const float*)d_in[20], *b5  = (const float*)d_in[21];

    float* out      = (float*)d_out;
    float* xrec_out = out + (size_t)8192 * 8192;
    float* z_out    = out + (size_t)8192 * 8192 + 8192 * 256;

    cudaFuncSetAttribute(k_mma<false, false>, cudaFuncAttributeMaxDynamicSharedMemorySize, SMEM_GEMM);
    cudaFuncSetAttribute(k_mma<true, true>,   cudaFuncAttributeMaxDynamicSharedMemorySize, SMEM_GEMM);

    __nv_bfloat16 *actA, *reB, *wB;
    float *xlr, *h, *re, *xd;
    cudaGetSymbolAddress((void**)&actA, g_actA);
    cudaGetSymbolAddress((void**)&reB,  g_reB);
    cudaGetSymbolAddress((void**)&wB,   g_wB);
    cudaGetSymbolAddress((void**)&xlr,  g_xlr);
    cudaGetSymbolAddress((void**)&h,    g_h);
    cudaGetSymbolAddress((void**)&re,   g_re);
    cudaGetSymbolAddress((void**)&xd,   g_xd);

    // CSR build
    k_init_deg<<<(N_NODES + 255) / 256, 256>>>();
    k_detect<<<(N_EDGES + 255) / 256, 256>>>((const unsigned int*)ei);
    k_hist<<<(N_EDGES + 255) / 256, 256>>>(ei);
    k_scan<<<1, 1024>>>();
    k_fill_edges<<<(N_EDGES + 255) / 256, 256>>>(ei);
    k_fill_loops<<<(N_NODES + 255) / 256, 256>>>();

    // weight splits (B-layout)
    k_split_w<<<1280, 256>>>(w1l, w1r, w2l, w2r, w3l, w3r, w4l, w4r, w5l, w5r);

    // Layer 1: x[8192,256] -> xl|xr [8192,256]
    k_split_act<<<8192 * 256 / 256, 256>>>(x, actA, nullptr, 256);
    k_mma<false, false><<<dim3(2, 64), 256, SMEM_GEMM>>>(actA, wB + 0 * 98304, xlr, 768, 256);
    k_agg<4><<<1024, 256>>>(xlr, 256, 128, a1, b1, h);

    // Layer 2: h[8192,128] -> z [8192,256]
    k_split_act<<<8192 * 128 / 256, 256>>>(h, actA, nullptr, 128);
    k_mma<false, false><<<dim3(4, 64), 256, SMEM_GEMM>>>(actA, wB + 2 * 98304, xlr, 384, 512);
    k_agg<8><<<1024, 256>>>(xlr, 512, 256, a2, b2, z_out);

    // split z once; used by layers 3 and 4
    k_split_act<<<8192 * 256 / 256, 256>>>(z_out, actA, nullptr, 256);

    // Layer 3 -> re
    k_mma<false, false><<<dim3(2, 64), 256, SMEM_GEMM>>>(actA, wB + 4 * 98304, xlr, 768, 256);
    k_agg<4><<<1024, 256>>>(xlr, 256, 128, a3, b3, re);

    // Layer 4 -> xd (still uses z's split in actA)
    k_mma<false, false><<<dim3(2, 64), 256, SMEM_GEMM>>>(actA, wB + 6 * 98304, xlr, 768, 256);
    k_agg<4><<<1024, 256>>>(xlr, 256, 128, a4, b4, xd);

    // Layer 5: xd[8192,128] -> x_rec [8192,256]
    k_split_act<<<8192 * 128 / 256, 256>>>(xd, actA, nullptr, 128);
    k_mma<false, false><<<dim3(4, 64), 256, SMEM_GEMM>>>(actA, wB + 8 * 98304, xlr, 384, 512);
    k_agg<8><<<1024, 256>>>(xlr, 512, 256, a5, b5, xrec_out);

    // recon_edge = sigmoid(re @ re.T), symmetric: upper tiles + mirrored write
    k_split_act<<<8192 * 128 / 256, 256>>>(re, actA, reB, 128);
    k_mma<true, true><<<dim3(64, 64), 256, SMEM_GEMM>>>(actA, reB, out, 384, 8192);
}

// round 6
// speedup vs baseline: 2.1732x; 1.0933x over previous
#include <cuda_runtime.h>
#include <cuda_bf16.h>
#include <math.h>
#include <stdint.h>

#define N_NODES 8192
#define N_EDGES 262144
#define N_TOT   (N_EDGES + N_NODES)

// ---------------- scratch (device globals; no cudaMalloc allowed) ----------
__device__ __align__(128) __nv_bfloat16 g_bufX[8192 * 768];   // x / z A-layout split
__device__ __align__(128) __nv_bfloat16 g_bufH[8192 * 384];   // h / xd A-layout split
__device__ __align__(128) __nv_bfloat16 g_reA [8192 * 384];   // re A-layout split
__device__ __align__(128) __nv_bfloat16 g_reB [8192 * 384];   // re B-layout split
__device__ __align__(128) __nv_bfloat16 g_wB  [10 * 98304];   // weight B-layout splits
__device__ __align__(128) float g_xlr[8192 * 512];
__device__ int g_deg[N_NODES];
__device__ int g_rowptr[N_NODES + 1];
__device__ int g_cursor[N_NODES];
__device__ int g_csrc[N_TOT];
__device__ int g_w64;

// ---------------- helpers ----------------------------------------------------
__device__ __forceinline__ uint32_t smem_u32(const void* p) {
    uint32_t a;
    asm("{ .reg .u64 t; cvta.to.shared.u64 t, %1; cvt.u32.u64 %0, t; }" : "=r"(a) : "l"(p));
    return a;
}
__device__ __forceinline__ void cp16(uint32_t dst, const void* src) {
    asm volatile("cp.async.cg.shared.global [%0], [%1], 16;" :: "r"(dst), "l"(src));
}
__device__ __forceinline__ void cp_commit() {
    asm volatile("cp.async.commit_group;" ::: "memory");
}
template <int N>
__device__ __forceinline__ void cp_wait() {
    asm volatile("cp.async.wait_group %0;" :: "n"(N) : "memory");
}
__device__ __forceinline__ void ldm4(uint32_t* r, uint32_t addr) {
    asm volatile("ldmatrix.sync.aligned.m8n8.x4.shared.b16 {%0,%1,%2,%3}, [%4];"
                 : "=r"(r[0]), "=r"(r[1]), "=r"(r[2]), "=r"(r[3]) : "r"(addr));
}
__device__ __forceinline__ void mma16816(float* c, const uint32_t* a, uint32_t b0, uint32_t b1) {
    asm volatile(
        "mma.sync.aligned.m16n8k16.row.col.f32.bf16.bf16.f32 "
        "{%0,%1,%2,%3}, {%4,%5,%6,%7}, {%8,%9}, {%0,%1,%2,%3};"
        : "+f"(c[0]), "+f"(c[1]), "+f"(c[2]), "+f"(c[3])
        : "r"(a[0]), "r"(a[1]), "r"(a[2]), "r"(a[3]), "r"(b0), "r"(b1));
}

// ---------------- CSR construction -----------------------------------------
__global__ void k_init_deg() {
    int i = blockIdx.x * blockDim.x + threadIdx.x;
    if (i == 0) g_w64 = 1;
    if (i < N_NODES) g_deg[i] = 1;
}
__global__ void k_detect(const unsigned int* __restrict__ w) {
    int i = blockIdx.x * blockDim.x + threadIdx.x;
    if (i < N_EDGES) {
        if (w[2 * i + 1] != 0u) g_w64 = 0;
    }
}
__device__ __forceinline__ int load_idx(const void* ei, int pos) {
    if (g_w64) return (int)((const long long*)ei)[pos];
    return ((const int*)ei)[pos];
}
__global__ void k_hist(const void* __restrict__ ei) {
    int e = blockIdx.x * blockDim.x + threadIdx.x;
    if (e < N_EDGES) atomicAdd(&g_deg[load_idx(ei, N_EDGES + e)], 1);
}
__global__ void k_scan() {
    __shared__ int wsum[32];
    int tid = threadIdx.x;
    int lane = tid & 31, w = tid >> 5;
    int base = tid * 8;
    int local[8];
    int run = 0;
#pragma unroll
    for (int j = 0; j < 8; j++) { local[j] = run; run += g_deg[base + j]; }
    int v = run;
#pragma unroll
    for (int o = 1; o < 32; o <<= 1) {
        int t = __shfl_up_sync(0xffffffffu, v, o);
        if (lane >= o) v += t;
    }
    if (lane == 31) wsum[w] = v;
    __syncthreads();
    if (w == 0) {
        int t = wsum[lane];
#pragma unroll
        for (int o = 1; o < 32; o <<= 1) {
            int u = __shfl_up_sync(0xffffffffu, t, o);
            if (lane >= o) t += u;
        }
        wsum[lane] = t;
    }
    __syncthreads();
    int exc = ((w == 0) ? 0 : wsum[w - 1]) + v - run;
#pragma unroll
    for (int j = 0; j < 8; j++) {
        g_rowptr[base + j] = exc + local[j];
        g_cursor[base + j] = exc + local[j];
    }
    if (tid == 1023) g_rowptr[N_NODES] = exc + run;
}
__global__ void k_fill_edges(const void* __restrict__ ei) {
    int e = blockIdx.x * blockDim.x + threadIdx.x;
    if (e < N_EDGES) {
        int s = load_idx(ei, e);
        int d = load_idx(ei, N_EDGES + e);
        g_csrc[atomicAdd(&g_cursor[d], 1)] = s;
    }
}
__global__ void k_fill_loops() {
    int i = blockIdx.x * blockDim.x + threadIdx.x;
    if (i < N_NODES) g_csrc[atomicAdd(&g_cursor[i], 1)] = i;
}

// ---------------- split-precision conversion (input x + weights only) -------
__global__ void k_split_act(const float* __restrict__ src,
                            __nv_bfloat16* __restrict__ dstA, int K) {
    int idx = blockIdx.x * blockDim.x + threadIdx.x;
    int m = idx / K, k = idx - m * K;
    float v = src[idx];
    __nv_bfloat16 hi = __float2bfloat16(v);
    __nv_bfloat16 lo = __float2bfloat16(v - __bfloat162float(hi));
    size_t b = (size_t)m * 3 * K + k;
    dstA[b] = hi; dstA[b + K] = lo; dstA[b + 2 * K] = hi;
}
__constant__ int c_wK[10] = {256, 256, 128, 128, 256, 256, 256, 256, 128, 128};
__global__ void k_split_w(const float* w0, const float* w1, const float* w2,
                          const float* w3, const float* w4, const float* w5,
                          const float* w6, const float* w7, const float* w8,
                          const float* w9) {
    const float* ws[10] = {w0, w1, w2, w3, w4, w5, w6, w7, w8, w9};
    int mid = blockIdx.x >> 7;
    int idx = (blockIdx.x & 127) * 256 + threadIdx.x;
    int K = c_wK[mid];
    int n = idx / K, k = idx - n * K;
    float v = ws[mid][idx];
    __nv_bfloat16 hi = __float2bfloat16(v);
    __nv_bfloat16 lo = __float2bfloat16(v - __bfloat162float(hi));
    __nv_bfloat16* dst = g_wB + (size_t)mid * 98304;
    size_t b = (size_t)n * 3 * K + k;
    dst[b] = hi; dst[b + K] = hi; dst[b + 2 * K] = lo;
}

// ---------------- HMMA GEMM: C[M,Nc] = A[M,Kp] * B[Nc,Kp]^T -----------------
#define SMEM_GEMM 65536

template <bool SIG, bool SYM>
__global__ void __launch_bounds__(256) k_mma(
    const __nv_bfloat16* __restrict__ A, const __nv_bfloat16* __restrict__ B,
    float* __restrict__ C, int Kp, int ldc)
{
    if (SYM && blockIdx.y > blockIdx.x) return;
    extern __shared__ char smem[];
    uint32_t sb = smem_u32(smem);
    const int tid = threadIdx.x;
    const int wid = tid >> 5, lane = tid & 31;
    const int m_base = (wid >> 1) * 32;
    const int n_base = (wid & 1) * 64;
    const int rowBase = blockIdx.y * 128;
    const int colBase = blockIdx.x * 128;

    float acc[2][8][4];
#pragma unroll
    for (int mi = 0; mi < 2; mi++)
#pragma unroll
        for (int ni = 0; ni < 8; ni++)
#pragma unroll
            for (int j = 0; j < 4; j++) acc[mi][ni][j] = 0.f;

#define LOADC(buf, ck) do {                                                    \
    const __nv_bfloat16* Ag = A + (size_t)rowBase * Kp + (ck) * 64;            \
    _Pragma("unroll")                                                          \
    for (int i = 0; i < 4; i++) {                                              \
        int idx = tid + i * 256;                                               \
        int r = idx >> 3, q = idx & 7;                                         \
        uint32_t off = (uint32_t)(r * 128 + q * 16);                           \
        off ^= (off >> 3) & 0x70;                                              \
        cp16(sb + (buf) * 16384 + off,                                         \
             (const char*)Ag + (size_t)r * Kp * 2 + q * 16);                   \
    }                                                                          \
    const __nv_bfloat16* Bg = B + (size_t)colBase * Kp + (ck) * 64;            \
    _Pragma("unroll")                                                          \
    for (int i = 0; i < 4; i++) {                                              \
        int idx = tid + i * 256;                                               \
        int r = idx >> 3, q = idx & 7;                                         \
        uint32_t off = (uint32_t)(r * 128 + q * 16);                           \
        off ^= (off >> 3) & 0x70;                                              \
        cp16(sb + 32768 + (buf) * 16384 + off,                                 \
             (const char*)Bg + (size_t)r * Kp * 2 + q * 16);                   \
    }                                                                          \
    cp_commit();                                                               \
} while (0)

    const int nc = Kp >> 6;
    LOADC(0, 0);
    for (int c = 0; c < nc; c++) {
        int buf = c & 1;
        if (c + 1 < nc) { LOADC(buf ^ 1, c + 1); cp_wait<1>(); }
        else cp_wait<0>();
        __syncthreads();
        uint32_t sbA = sb + buf * 16384;
        uint32_t sbB = sb + 32768 + buf * 16384;
#pragma unroll
        for (int ks = 0; ks < 4; ks++) {
            uint32_t a[2][4];
#pragma unroll
            for (int mi = 0; mi < 2; mi++) {
                uint32_t off = (uint32_t)((m_base + mi * 16 + (lane & 15)) * 128
                                          + ks * 32 + ((lane >> 4) << 4));
                off ^= (off >> 3) & 0x70;
                ldm4(a[mi], sbA + off);
            }
            uint32_t b[4][4];
#pragma unroll
            for (int p = 0; p < 4; p++) {
                uint32_t off = (uint32_t)((n_base + p * 16 + (lane & 7) + ((lane >> 4) << 3)) * 128
                                          + ks * 32 + (((lane >> 3) & 1) << 4));
                off ^= (off >> 3) & 0x70;
                ldm4(b[p], sbB + off);
            }
#pragma unroll
            for (int mi = 0; mi < 2; mi++)
#pragma unroll
                for (int ni = 0; ni < 8; ni++)
                    mma16816(acc[mi][ni], a[mi], b[ni >> 1][(ni & 1) * 2],
                             b[ni >> 1][(ni & 1) * 2 + 1]);
        }
        __syncthreads();
    }

    if (SIG) {
#pragma unroll
        for (int mi = 0; mi < 2; mi++)
#pragma unroll
            for (int ni = 0; ni < 8; ni++)
#pragma unroll
                for (int j = 0; j < 4; j++)
                    acc[mi][ni][j] = 1.f / (1.f + __expf(-acc[mi][ni][j]));
    }

#pragma unroll
    for (int mi = 0; mi < 2; mi++) {
        int gr = rowBase + m_base + mi * 16 + (lane >> 2);
#pragma unroll
        for (int ni = 0; ni < 8; ni++) {
            int gc = colBase + n_base + ni * 8 + (lane & 3) * 2;
            *(float2*)&C[(size_t)gr * ldc + gc] = make_float2(acc[mi][ni][0], acc[mi][ni][1]);
            *(float2*)&C[(size_t)(gr + 8) * ldc + gc] = make_float2(acc[mi][ni][2], acc[mi][ni][3]);
        }
    }

    if (SYM) {
        float* sT = (float*)smem;
#pragma unroll
        for (int nh = 0; nh < 2; nh++) {
            __syncthreads();
            if ((wid & 1) == nh) {
#pragma unroll
                for (int mi = 0; mi < 2; mi++) {
                    int ml = m_base + mi * 16 + (lane >> 2);
#pragma unroll
                    for (int ni = 0; ni < 8; ni++) {
                        int cl = ni * 8 + (lane & 3) * 2;
                        sT[cl * 132 + ml]           = acc[mi][ni][0];
                        sT[(cl + 1) * 132 + ml]     = acc[mi][ni][1];
                        sT[cl * 132 + ml + 8]       = acc[mi][ni][2];
                        sT[(cl + 1) * 132 + ml + 8] = acc[mi][ni][3];
                    }
                }
            }
            __syncthreads();
            int n_loc = tid >> 2;
#pragma unroll
            for (int it = 0; it < 8; it++) {
                int m4 = (tid & 3) * 32 + it * 4;
                float4 v = *(float4*)&sT[n_loc * 132 + m4];
                *(float4*)&C[(size_t)(colBase + nh * 64 + n_loc) * ldc + rowBase + m4] = v;
            }
        }
    }
#undef LOADC
}

// ---------------- GATv2 agg with fused split epilogue ------------------------
template <int CPL, bool OUT, bool SPA, bool SPB>
__global__ __launch_bounds__(256) void k_agg(
    const float* __restrict__ xlr, int S, int xrOff,
    const float* __restrict__ att, const float* __restrict__ bias,
    float* __restrict__ out, __nv_bfloat16* __restrict__ dstA,
    __nv_bfloat16* __restrict__ dstB)
{
    const int CH = CPL * 32;
    int warp = blockIdx.x * (blockDim.x >> 5) + (threadIdx.x >> 5);
    int lane = threadIdx.x & 31;
    if (warp >= N_NODES) return;

    float xrv[CPL], av[CPL], acc[CPL];
#pragma unroll
    for (int c = 0; c < CPL; c++) {
        int ch = lane + c * 32;
        xrv[c] = xlr[(size_t)warp * S + xrOff + ch];
        av[c]  = att[ch];
        acc[c] = 0.f;
    }
    float m = -3.0e38f, s = 0.f;
    int beg = g_rowptr[warp], end = g_rowptr[warp + 1];
    for (int e = beg; e < end; e++) {
        int src = g_csrc[e];
        float xs[CPL];
        float part = 0.f;
#pragma unroll
        for (int c = 0; c < CPL; c++) {
            xs[c] = xlr[(size_t)src * S + lane + c * 32];
            float t = xs[c] + xrv[c];
            float lr = t > 0.f ? t : 0.2f * t;
            part += av[c] * lr;
        }
#pragma unroll
        for (int o = 16; o > 0; o >>= 1)
            part += __shfl_xor_sync(0xffffffffu, part, o);
        float mn = fmaxf(m, part);
        float sc = __expf(m - mn);
        float p  = __expf(part - mn);
        s = s * sc + p;
#pragma unroll
        for (int c = 0; c < CPL; c++) acc[c] = acc[c] * sc + p * xs[c];
        m = mn;
    }
    float inv = 1.f / s;
#pragma unroll
    for (int c = 0; c < CPL; c++) {
        int ch = lane + c * 32;
        float v = acc[c] * inv + bias[ch];
        v = fmaxf(v, 0.f);
        if (OUT) out[(size_t)warp * CH + ch] = v;
        if (SPA || SPB) {
            __nv_bfloat16 hi = __float2bfloat16(v);
            __nv_bfloat16 lo = __float2bfloat16(v - __bfloat162float(hi));
            size_t b = (size_t)warp * 3 * CH + ch;
            if (SPA) { dstA[b] = hi; dstA[b + CH] = lo; dstA[b + 2 * CH] = hi; }
            if (SPB) { dstB[b] = hi; dstB[b + CH] = hi; dstB[b + 2 * CH] = lo; }
        }
    }
}

// ---------------- launcher ---------------------------------------------------
extern "C" void kernel_launch(void* const* d_in, const int* in_sizes, int n_in,
                              void* d_out, int out_size)
{
    const float* x  = (const float*)d_in[0];
    const void*  ei = d_in[1];
    const float* w1l = (const float*)d_in[2],  *w1r = (const float*)d_in[3];
    const float* a1  = (const float*)d_in[4],  *b1  = (const float*)d_in[5];
    const float* w2l = (const float*)d_in[6],  *w2r = (const float*)d_in[7];
    const float* a2  = (const float*)d_in[8],  *b2  = (const float*)d_in[9];
    const float* w3l = (const float*)d_in[10], *w3r = (const float*)d_in[11];
    const float* a3  = (const float*)d_in[12], *b3  = (const float*)d_in[13];
    const float* w4l = (const float*)d_in[14], *w4r = (const float*)d_in[15];
    const float* a4  = (const float*)d_in[16], *b4  = (const float*)d_in[17];
    const float* w5l = (const float*)d_in[18], *w5r = (const float*)d_in[19];
    const float* a5  = (const float*)d_in[20], *b5  = (const float*)d_in[21];

    float* out      = (float*)d_out;
    float* xrec_out = out + (size_t)8192 * 8192;
    float* z_out    = out + (size_t)8192 * 8192 + 8192 * 256;

    static cudaStream_t s2 = nullptr;
    static cudaEvent_t evF0 = nullptr, evCSR = nullptr, evF1 = nullptr, evRC = nullptr;
    if (!s2) {
        cudaStreamCreateWithFlags(&s2, cudaStreamNonBlocking);
        cudaEventCreateWithFlags(&evF0,  cudaEventDisableTiming);
        cudaEventCreateWithFlags(&evCSR, cudaEventDisableTiming);
        cudaEventCreateWithFlags(&evF1,  cudaEventDisableTiming);
        cudaEventCreateWithFlags(&evRC,  cudaEventDisableTiming);
        cudaFuncSetAttribute(k_mma<false, false>, cudaFuncAttributeMaxDynamicSharedMemorySize, SMEM_GEMM);
        cudaFuncSetAttribute(k_mma<true, true>,   cudaFuncAttributeMaxDynamicSharedMemorySize, SMEM_GEMM);
    }

    __nv_bfloat16 *bufX, *bufH, *reA, *reB, *wB;
    float *xlr;
    cudaGetSymbolAddress((void**)&bufX, g_bufX);
    cudaGetSymbolAddress((void**)&bufH, g_bufH);
    cudaGetSymbolAddress((void**)&reA,  g_reA);
    cudaGetSymbolAddress((void**)&reB,  g_reB);
    cudaGetSymbolAddress((void**)&wB,   g_wB);
    cudaGetSymbolAddress((void**)&xlr,  g_xlr);

    // ---- fork: CSR build on side stream ----
    cudaEventRecord(evF0, 0);
    cudaStreamWaitEvent(s2, evF0, 0);
    k_init_deg<<<(N_NODES + 255) / 256, 256, 0, s2>>>();
    k_detect<<<(N_EDGES + 255) / 256, 256, 0, s2>>>((const unsigned int*)ei);
    k_hist<<<(N_EDGES + 255) / 256, 256, 0, s2>>>(ei);
    k_scan<<<1, 1024, 0, s2>>>();
    k_fill_edges<<<(N_EDGES + 255) / 256, 256, 0, s2>>>(ei);
    k_fill_loops<<<(N_NODES + 255) / 256, 256, 0, s2>>>();
    cudaEventRecord(evCSR, s2);

    // ---- main: weight + input splits, layer-1 GEMM (overlapped with CSR) ----
    k_split_w<<<1280, 256>>>(w1l, w1r, w2l, w2r, w3l, w3r, w4l, w4r, w5l, w5r);
    k_split_act<<<8192 * 256 / 256, 256>>>(x, bufX, 256);
    k_mma<false, false><<<dim3(2, 64), 256, SMEM_GEMM>>>(bufX, wB + 0 * 98304, xlr, 768, 256);
    cudaStreamWaitEvent(0, evCSR, 0);

    // Layer 1 agg -> h split only
    k_agg<4, false, true, false><<<1024, 256>>>(xlr, 256, 128, a1, b1, nullptr, bufH, nullptr);

    // Layer 2: h -> z (output + split into bufX)
    k_mma<false, false><<<dim3(4, 64), 256, SMEM_GEMM>>>(bufH, wB + 2 * 98304, xlr, 384, 512);
    k_agg<8, true, true, false><<<1024, 256>>>(xlr, 512, 256, a2, b2, z_out, bufX, nullptr);

    // Layer 3: z -> re splits (A + B layouts), no fp32
    k_mma<false, false><<<dim3(2, 64), 256, SMEM_GEMM>>>(bufX, wB + 4 * 98304, xlr, 768, 256);
    k_agg<4, false, true, true><<<1024, 256>>>(xlr, 256, 128, a3, b3, nullptr, reA, reB);

    // ---- fork: recon on side stream, concurrent with layers 4/5 ----
    cudaEventRecord(evF1, 0);
    cudaStreamWaitEvent(s2, evF1, 0);
    k_mma<true, true><<<dim3(64, 64), 256, SMEM_GEMM, s2>>>(reA, reB, out, 384, 8192);
    cudaEventRecord(evRC, s2);

    // Layer 4: z -> xd split
    k_mma<false, false><<<dim3(2, 64), 256, SMEM_GEMM>>>(bufX, wB + 6 * 98304, xlr, 768, 256);
    k_agg<4, false, true, false><<<1024, 256>>>(xlr, 256, 128, a4, b4, nullptr, bufH, nullptr);

    // Layer 5: xd -> x_rec
    k_mma<false, false><<<dim3(4, 64), 256, SMEM_GEMM>>>(bufH, wB + 8 * 98304, xlr, 384, 512);
    k_agg<8, true, false, false><<<1024, 256>>>(xlr, 512, 256, a5, b5, xrec_out, nullptr, nullptr);

    // ---- join ----
    cudaStreamWaitEvent(0, evRC, 0);
}

// round 8
// speedup vs baseline: 2.2774x; 1.0479x over previous
#include <cuda_runtime.h>
#include <cuda_bf16.h>
#include <math.h>
#include <stdint.h>

#define N_NODES 8192
#define N_EDGES 262144
#define N_TOT   (N_EDGES + N_NODES)

// ---------------- scratch (device globals; no cudaMalloc allowed) ----------
__device__ __align__(128) __nv_bfloat16 g_bufX[8192 * 768];   // x / z A-layout split
__device__ __align__(128) __nv_bfloat16 g_bufH[8192 * 384];   // h / xd A-layout split
__device__ __align__(128) __nv_bfloat16 g_reA [8192 * 384];   // re A-layout split
__device__ __align__(128) __nv_bfloat16 g_reB [8192 * 384];   // re B-layout split
__device__ __align__(128) __nv_bfloat16 g_wB  [10 * 98304];   // weight B-layout splits
__device__ __align__(128) float g_xlr[8192 * 512];
__device__ int g_deg[N_NODES];
__device__ int g_rowptr[N_NODES + 1];
__device__ int g_cursor[N_NODES];
__device__ int g_csrc[N_TOT];
__device__ int g_w64;

// ---------------- helpers ----------------------------------------------------
__device__ __forceinline__ uint32_t smem_u32(const void* p) {
    uint32_t a;
    asm("{ .reg .u64 t; cvta.to.shared.u64 t, %1; cvt.u32.u64 %0, t; }" : "=r"(a) : "l"(p));
    return a;
}
__device__ __forceinline__ void cp16(uint32_t dst, const void* src) {
    asm volatile("cp.async.cg.shared.global [%0], [%1], 16;" :: "r"(dst), "l"(src));
}
__device__ __forceinline__ void cp_commit() {
    asm volatile("cp.async.commit_group;" ::: "memory");
}
template <int N>
__device__ __forceinline__ void cp_wait() {
    asm volatile("cp.async.wait_group %0;" :: "n"(N) : "memory");
}
__device__ __forceinline__ void ldm4(uint32_t* r, uint32_t addr) {
    asm volatile("ldmatrix.sync.aligned.m8n8.x4.shared.b16 {%0,%1,%2,%3}, [%4];"
                 : "=r"(r[0]), "=r"(r[1]), "=r"(r[2]), "=r"(r[3]) : "r"(addr));
}
__device__ __forceinline__ void mma16816(float* c, const uint32_t* a, uint32_t b0, uint32_t b1) {
    asm volatile(
        "mma.sync.aligned.m16n8k16.row.col.f32.bf16.bf16.f32 "
        "{%0,%1,%2,%3}, {%4,%5,%6,%7}, {%8,%9}, {%0,%1,%2,%3};"
        : "+f"(c[0]), "+f"(c[1]), "+f"(c[2]), "+f"(c[3])
        : "r"(a[0]), "r"(a[1]), "r"(a[2]), "r"(a[3]), "r"(b0), "r"(b1));
}

// ---------------- CSR construction -----------------------------------------
__global__ void k_csr_init(const unsigned int* __restrict__ w) {
    int i = blockIdx.x * blockDim.x + threadIdx.x;
    if (i == 0) g_w64 = 1;
    if (i < N_NODES) g_deg[i] = 1;                 // self loop
    // int64 detection: odd words all zero iff int64
    for (int e = i; e < N_EDGES; e += gridDim.x * blockDim.x)
        if (w[2 * e + 1] != 0u) { g_w64 = 0; break; }
}
__device__ __forceinline__ int load_idx(const void* ei, int pos) {
    if (g_w64) return (int)((const long long*)ei)[pos];
    return ((const int*)ei)[pos];
}
__global__ void k_hist(const void* __restrict__ ei) {
    int e = blockIdx.x * blockDim.x + threadIdx.x;
    if (e < N_EDGES) atomicAdd(&g_deg[load_idx(ei, N_EDGES + e)], 1);
}
__global__ void k_scan() {
    __shared__ int wsum[32];
    int tid = threadIdx.x;
    int lane = tid & 31, w = tid >> 5;
    int base = tid * 8;
    int local[8];
    int run = 0;
#pragma unroll
    for (int j = 0; j < 8; j++) { local[j] = run; run += g_deg[base + j]; }
    int v = run;
#pragma unroll
    for (int o = 1; o < 32; o <<= 1) {
        int t = __shfl_up_sync(0xffffffffu, v, o);
        if (lane >= o) v += t;
    }
    if (lane == 31) wsum[w] = v;
    __syncthreads();
    if (w == 0) {
        int t = wsum[lane];
#pragma unroll
        for (int o = 1; o < 32; o <<= 1) {
            int u = __shfl_up_sync(0xffffffffu, t, o);
            if (lane >= o) t += u;
        }
        wsum[lane] = t;
    }
    __syncthreads();
    int exc = ((w == 0) ? 0 : wsum[w - 1]) + v - run;
#pragma unroll
    for (int j = 0; j < 8; j++) {
        g_rowptr[base + j] = exc + local[j];
        g_cursor[base + j] = exc + local[j];
    }
    if (tid == 1023) g_rowptr[N_NODES] = exc + run;
}
__global__ void k_fill(const void* __restrict__ ei) {
    int e = blockIdx.x * blockDim.x + threadIdx.x;
    if (e < N_EDGES) {
        int s = load_idx(ei, e);
        int d = load_idx(ei, N_EDGES + e);
        g_csrc[atomicAdd(&g_cursor[d], 1)] = s;
    } else if (e < N_TOT) {
        int i = e - N_EDGES;
        g_csrc[atomicAdd(&g_cursor[i], 1)] = i;
    }
}

// ---------------- split-precision conversion (input x + weights only) -------
__global__ void k_split_act(const float* __restrict__ src,
                            __nv_bfloat16* __restrict__ dstA, int K) {
    int idx = blockIdx.x * blockDim.x + threadIdx.x;
    int m = idx / K, k = idx - m * K;
    float v = src[idx];
    __nv_bfloat16 hi = __float2bfloat16(v);
    __nv_bfloat16 lo = __float2bfloat16(v - __bfloat162float(hi));
    size_t b = (size_t)m * 3 * K + k;
    dstA[b] = hi; dstA[b + K] = lo; dstA[b + 2 * K] = hi;
}
__constant__ int c_wK[10] = {256, 256, 128, 128, 256, 256, 256, 256, 128, 128};
__global__ void k_split_w(const float* w0, const float* w1, const float* w2,
                          const float* w3, const float* w4, const float* w5,
                          const float* w6, const float* w7, const float* w8,
                          const float* w9) {
    const float* ws[10] = {w0, w1, w2, w3, w4, w5, w6, w7, w8, w9};
    int mid = blockIdx.x >> 7;
    int idx = (blockIdx.x & 127) * 256 + threadIdx.x;
    int K = c_wK[mid];
    int n = idx / K, k = idx - n * K;
    float v = ws[mid][idx];
    __nv_bfloat16 hi = __float2bfloat16(v);
    __nv_bfloat16 lo = __float2bfloat16(v - __bfloat162float(hi));
    __nv_bfloat16* dst = g_wB + (size_t)mid * 98304;
    size_t b = (size_t)n * 3 * K + k;
    dst[b] = hi; dst[b + K] = hi; dst[b + 2 * K] = lo;
}

// ---------------- HMMA GEMM: C[M,Nc] = A[M,Kp] * B[Nc,Kp]^T -----------------
// 128x128 block tile, 8 warps (32x64), K-chunk 64, SW128 smem, 3-stage cp.async.
#define SMEM_GEMM 98304

template <bool SIG, bool SYM>
__global__ void __launch_bounds__(256) k_mma(
    const __nv_bfloat16* __restrict__ A, const __nv_bfloat16* __restrict__ B,
    float* __restrict__ C, int Kp, int ldc)
{
    if (SYM && blockIdx.y > blockIdx.x) return;
    extern __shared__ char smem[];
    uint32_t sb = smem_u32(smem);
    const int tid = threadIdx.x;
    const int wid = tid >> 5, lane = tid & 31;
    const int m_base = (wid >> 1) * 32;
    const int n_base = (wid & 1) * 64;
    const int rowBase = blockIdx.y * 128;
    const int colBase = blockIdx.x * 128;

    float acc[2][8][4];
#pragma unroll
    for (int mi = 0; mi < 2; mi++)
#pragma unroll
        for (int ni = 0; ni < 8; ni++)
#pragma unroll
            for (int j = 0; j < 4; j++) acc[mi][ni][j] = 0.f;

#define LOADC(buf, ck) do {                                                    \
    const __nv_bfloat16* Ag = A + (size_t)rowBase * Kp + (ck) * 64;            \
    _Pragma("unroll")                                                          \
    for (int i = 0; i < 4; i++) {                                              \
        int idx = tid + i * 256;                                               \
        int r = idx >> 3, q = idx & 7;                                         \
        uint32_t off = (uint32_t)(r * 128 + q * 16);                           \
        off ^= (off >> 3) & 0x70;                                              \
        cp16(sb + (buf) * 32768 + off,                                         \
             (const char*)Ag + (size_t)r * Kp * 2 + q * 16);                   \
    }                                                                          \
    const __nv_bfloat16* Bg = B + (size_t)colBase * Kp + (ck) * 64;            \
    _Pragma("unroll")                                                          \
    for (int i = 0; i < 4; i++) {                                              \
        int idx = tid + i * 256;                                               \
        int r = idx >> 3, q = idx & 7;                                         \
        uint32_t off = (uint32_t)(r * 128 + q * 16);                           \
        off ^= (off >> 3) & 0x70;                                              \
        cp16(sb + (buf) * 32768 + 16384 + off,                                 \
             (const char*)Bg + (size_t)r * Kp * 2 + q * 16);                   \
    }                                                                          \
    cp_commit();                                                               \
} while (0)

    const int nc = Kp >> 6;
    LOADC(0, 0);
    if (nc > 1) LOADC(1, 1);
    int buf = 0;
    for (int c = 0; c < nc; c++) {
        if (c + 2 < nc) { LOADC((buf + 2) % 3, c + 2); cp_wait<2>(); }
        else if (c + 1 < nc) cp_wait<1>();
        else cp_wait<0>();
        __syncthreads();
        uint32_t sbA = sb + buf * 32768;
        uint32_t sbB = sbA + 16384;
#pragma unroll
        for (int ks = 0; ks < 4; ks++) {
            uint32_t a[2][4];
#pragma unroll
            for (int mi = 0; mi < 2; mi++) {
                uint32_t off = (uint32_t)((m_base + mi * 16 + (lane & 15)) * 128
                                          + ks * 32 + ((lane >> 4) << 4));
                off ^= (off >> 3) & 0x70;
                ldm4(a[mi], sbA + off);
            }
            uint32_t b[4][4];
#pragma unroll
            for (int p = 0; p < 4; p++) {
                uint32_t off = (uint32_t)((n_base + p * 16 + (lane & 7) + ((lane >> 4) << 3)) * 128
                                          + ks * 32 + (((lane >> 3) & 1) << 4));
                off ^= (off >> 3) & 0x70;
                ldm4(b[p], sbB + off);
            }
#pragma unroll
            for (int mi = 0; mi < 2; mi++)
#pragma unroll
                for (int ni = 0; ni < 8; ni++)
                    mma16816(acc[mi][ni], a[mi], b[ni >> 1][(ni & 1) * 2],
                             b[ni >> 1][(ni & 1) * 2 + 1]);
        }
        __syncthreads();
        buf = (buf + 1) % 3;
    }

    if (SIG) {
#pragma unroll
        for (int mi = 0; mi < 2; mi++)
#pragma unroll
            for (int ni = 0; ni < 8; ni++)
#pragma unroll
                for (int j = 0; j < 4; j++)
                    acc[mi][ni][j] = 1.f / (1.f + __expf(-acc[mi][ni][j]));
    }

#pragma unroll
    for (int mi = 0; mi < 2; mi++) {
        int gr = rowBase + m_base + mi * 16 + (lane >> 2);
#pragma unroll
        for (int ni = 0; ni < 8; ni++) {
            int gc = colBase + n_base + ni * 8 + (lane & 3) * 2;
            *(float2*)&C[(size_t)gr * ldc + gc] = make_float2(acc[mi][ni][0], acc[mi][ni][1]);
            *(float2*)&C[(size_t)(gr + 8) * ldc + gc] = make_float2(acc[mi][ni][2], acc[mi][ni][3]);
        }
    }

    if (SYM) {
        float* sT = (float*)smem;
#pragma unroll
        for (int nh = 0; nh < 2; nh++) {
            __syncthreads();
            if ((wid & 1) == nh) {
#pragma unroll
                for (int mi = 0; mi < 2; mi++) {
                    int ml = m_base + mi * 16 + (lane >> 2);
#pragma unroll
                    for (int ni = 0; ni < 8; ni++) {
                        int cl = ni * 8 + (lane & 3) * 2;
                        sT[cl * 132 + ml]           = acc[mi][ni][0];
                        sT[(cl + 1) * 132 + ml]     = acc[mi][ni][1];
                        sT[cl * 132 + ml + 8]       = acc[mi][ni][2];
                        sT[(cl + 1) * 132 + ml + 8] = acc[mi][ni][3];
                    }
                }
            }
            __syncthreads();
            int n_loc = tid >> 2;
#pragma unroll
            for (int it = 0; it < 8; it++) {
                int m4 = (tid & 3) * 32 + it * 4;
                float4 v = *(float4*)&sT[n_loc * 132 + m4];
                *(float4*)&C[(size_t)(colBase + nh * 64 + n_loc) * ldc + rowBase + m4] = v;
            }
        }
    }
#undef LOADC
}

// ---------------- GATv2 agg, unroll-2 pipelined, fused split epilogue --------
template <int CPL, bool OUT, bool SPA, bool SPB>
__global__ __launch_bounds__(256) void k_agg(
    const float* __restrict__ xlr, int S, int xrOff,
    const float* __restrict__ att, const float* __restrict__ bias,
    float* __restrict__ out, __nv_bfloat16* __restrict__ dstA,
    __nv_bfloat16* __restrict__ dstB)
{
    const int CH = CPL * 32;
    int warp = blockIdx.x * (blockDim.x >> 5) + (threadIdx.x >> 5);
    int lane = threadIdx.x & 31;
    if (warp >= N_NODES) return;

    float xrv[CPL], av[CPL], acc[CPL];
#pragma unroll
    for (int c = 0; c < CPL; c++) {
        int ch = lane + c * 32;
        xrv[c] = xlr[(size_t)warp * S + xrOff + ch];
        av[c]  = att[ch];
        acc[c] = 0.f;
    }
    float m = -3.0e38f, s = 0.f;
    int beg = g_rowptr[warp], end = g_rowptr[warp + 1];
    int e = beg;
    for (; e + 1 < end; e += 2) {
        int s0 = g_csrc[e], s1 = g_csrc[e + 1];
        float xs0[CPL], xs1[CPL];
        float p0 = 0.f, p1 = 0.f;
#pragma unroll
        for (int c = 0; c < CPL; c++) {
            xs0[c] = xlr[(size_t)s0 * S + lane + c * 32];
            xs1[c] = xlr[(size_t)s1 * S + lane + c * 32];
        }
#pragma unroll
        for (int c = 0; c < CPL; c++) {
            float t0 = xs0[c] + xrv[c];
            float t1 = xs1[c] + xrv[c];
            p0 += av[c] * (t0 > 0.f ? t0 : 0.2f * t0);
            p1 += av[c] * (t1 > 0.f ? t1 : 0.2f * t1);
        }
#pragma unroll
        for (int o = 16; o > 0; o >>= 1) {
            p0 += __shfl_xor_sync(0xffffffffu, p0, o);
            p1 += __shfl_xor_sync(0xffffffffu, p1, o);
        }
        {
            float mn = fmaxf(m, p0);
            float sc = __expf(m - mn), p = __expf(p0 - mn);
            s = s * sc + p;
#pragma unroll
            for (int c = 0; c < CPL; c++) acc[c] = acc[c] * sc + p * xs0[c];
            m = mn;
        }
        {
            float mn = fmaxf(m, p1);
            float sc = __expf(m - mn), p = __expf(p1 - mn);
            s = s * sc + p;
#pragma unroll
            for (int c = 0; c < CPL; c++) acc[c] = acc[c] * sc + p * xs1[c];
            m = mn;
        }
    }
    if (e < end) {
        int src = g_csrc[e];
        float xs[CPL];
        float part = 0.f;
#pragma unroll
        for (int c = 0; c < CPL; c++) {
            xs[c] = xlr[(size_t)src * S + lane + c * 32];
            float t = xs[c] + xrv[c];
            part += av[c] * (t > 0.f ? t : 0.2f * t);
        }
#pragma unroll
        for (int o = 16; o > 0; o >>= 1)
            part += __shfl_xor_sync(0xffffffffu, part, o);
        float mn = fmaxf(m, part);
        float sc = __expf(m - mn), p = __expf(part - mn);
        s = s * sc + p;
#pragma unroll
        for (int c = 0; c < CPL; c++) acc[c] = acc[c] * sc + p * xs[c];
        m = mn;
    }
    float inv = 1.f / s;
#pragma unroll
    for (int c = 0; c < CPL; c++) {
        int ch = lane + c * 32;
        float v = acc[c] * inv + bias[ch];
        v = fmaxf(v, 0.f);
        if (OUT) out[(size_t)warp * CH + ch] = v;
        if (SPA || SPB) {
            __nv_bfloat16 hi = __float2bfloat16(v);
            __nv_bfloat16 lo = __float2bfloat16(v - __bfloat162float(hi));
            size_t b = (size_t)warp * 3 * CH + ch;
            if (SPA) { dstA[b] = hi; dstA[b + CH] = lo; dstA[b + 2 * CH] = hi; }
            if (SPB) { dstB[b] = hi; dstB[b + CH] = hi; dstB[b + 2 * CH] = lo; }
        }
    }
}

// ---------------- launcher ---------------------------------------------------
extern "C" void kernel_launch(void* const* d_in, const int* in_sizes, int n_in,
                              void* d_out, int out_size)
{
    const float* x  = (const float*)d_in[0];
    const void*  ei = d_in[1];
    const float* w1l = (const float*)d_in[2],  *w1r = (const float*)d_in[3];
    const float* a1  = (const float*)d_in[4],  *b1  = (const float*)d_in[5];
    const float* w2l = (const float*)d_in[6],  *w2r = (const float*)d_in[7];
    const float* a2  = (const float*)d_in[8],  *b2  = (const float*)d_in[9];
    const float* w3l = (const float*)d_in[10], *w3r = (const float*)d_in[11];
    const float* a3  = (const float*)d_in[12], *b3  = (const float*)d_in[13];
    const float* w4l = (const float*)d_in[14], *w4r = (const float*)d_in[15];
    const float* a4  = (const float*)d_in[16], *b4  = (const float*)d_in[17];
    const float* w5l = (const float*)d_in[18], *w5r = (const float*)d_in[19];
    const float* a5  = (const float*)d_in[20], *b5  = (const float*)d_in[21];

    float* out      = (float*)d_out;
    float* xrec_out = out + (size_t)8192 * 8192;
    float* z_out    = out + (size_t)8192 * 8192 + 8192 * 256;

    static cudaStream_t s2 = nullptr;
    static cudaEvent_t evF0 = nullptr, evCSR = nullptr, evF1 = nullptr, evRC = nullptr;
    if (!s2) {
        cudaStreamCreateWithFlags(&s2, cudaStreamNonBlocking);
        cudaEventCreateWithFlags(&evF0,  cudaEventDisableTiming);
        cudaEventCreateWithFlags(&evCSR, cudaEventDisableTiming);
        cudaEventCreateWithFlags(&evF1,  cudaEventDisableTiming);
        cudaEventCreateWithFlags(&evRC,  cudaEventDisableTiming);
        cudaFuncSetAttribute(k_mma<false, false>, cudaFuncAttributeMaxDynamicSharedMemorySize, SMEM_GEMM);
        cudaFuncSetAttribute(k_mma<true, true>,   cudaFuncAttributeMaxDynamicSharedMemorySize, SMEM_GEMM);
    }

    __nv_bfloat16 *bufX, *bufH, *reA, *reB, *wB;
    float *xlr;
    cudaGetSymbolAddress((void**)&bufX, g_bufX);
    cudaGetSymbolAddress((void**)&bufH, g_bufH);
    cudaGetSymbolAddress((void**)&reA,  g_reA);
    cudaGetSymbolAddress((void**)&reB,  g_reB);
    cudaGetSymbolAddress((void**)&wB,   g_wB);
    cudaGetSymbolAddress((void**)&xlr,  g_xlr);

    // ---- fork: CSR build on side stream ----
    cudaEventRecord(evF0, 0);
    cudaStreamWaitEvent(s2, evF0, 0);
    k_csr_init<<<64, 256, 0, s2>>>((const unsigned int*)ei);
    k_hist<<<(N_EDGES + 255) / 256, 256, 0, s2>>>(ei);
    k_scan<<<1, 1024, 0, s2>>>();
    k_fill<<<(N_TOT + 255) / 256, 256, 0, s2>>>(ei);
    cudaEventRecord(evCSR, s2);

    // ---- main: weight + input splits, layer-1 GEMM (overlapped with CSR) ----
    k_split_w<<<1280, 256>>>(w1l, w1r, w2l, w2r, w3l, w3r, w4l, w4r, w5l, w5r);
    k_split_act<<<8192 * 256 / 256, 256>>>(x, bufX, 256);
    k_mma<false, false><<<dim3(2, 64), 256, SMEM_GEMM>>>(bufX, wB + 0 * 98304, xlr, 768, 256);
    cudaStreamWaitEvent(0, evCSR, 0);

    // Layer 1 agg -> h split only
    k_agg<4, false, true, false><<<1024, 256>>>(xlr, 256, 128, a1, b1, nullptr, bufH, nullptr);

    // Layer 2: h -> z (output + split into bufX)
    k_mma<false, false><<<dim3(4, 64), 256, SMEM_GEMM>>>(bufH, wB + 2 * 98304, xlr, 384, 512);
    k_agg<8, true, true, false><<<1024, 256>>>(xlr, 512, 256, a2, b2, z_out, bufX, nullptr);

    // Layer 3: z -> re splits (A + B layouts), no fp32
    k_mma<false, false><<<dim3(2, 64), 256, SMEM_GEMM>>>(bufX, wB + 4 * 98304, xlr, 768, 256);
    k_agg<4, false, true, true><<<1024, 256>>>(xlr, 256, 128, a3, b3, nullptr, reA, reB);

    // ---- fork: recon on side stream, concurrent with layers 4/5 ----
    cudaEventRecord(evF1, 0);
    cudaStreamWaitEvent(s2, evF1, 0);
    k_mma<true, true><<<dim3(64, 64), 256, SMEM_GEMM, s2>>>(reA, reB, out, 384, 8192);
    cudaEventRecord(evRC, s2);

    // Layer 4: z -> xd split
    k_mma<false, false><<<dim3(2, 64), 256, SMEM_GEMM>>>(bufX, wB + 6 * 98304, xlr, 768, 256);
    k_agg<4, false, true, false><<<1024, 256>>>(xlr, 256, 128, a4, b4, nullptr, bufH, nullptr);

    // Layer 5: xd -> x_rec
    k_mma<false, false><<<dim3(4, 64), 256, SMEM_GEMM>>>(bufH, wB + 8 * 98304, xlr, 384, 512);
    k_agg<8, true, false, false><<<1024, 256>>>(xlr, 512, 256, a5, b5, xrec_out, nullptr, nullptr);

    // ---- join ----
    cudaStreamWaitEvent(0, evRC, 0);
}